// round 11
// baseline (speedup 1.0000x reference)
#include <cuda_runtime.h>
#include <cstdint>

#define B_      2
#define I_      1024
#define J_      1024
#define C_      64
#define TJ      32
#define NT      (J_/TJ)     // 32
#define ROWS    2
#define THREADS 64
#define KPAD    17          // float4 per K row in smem (conflict-free)

typedef unsigned long long ull;

// sigmoid(x) = 0.5 + sgn(x)*(P(e)-0.5), e = 2^(-log2e*|x|), P quartic minimax of 1/(1+e) on [0,1]
#define PC4  0.156867f
#define PC3 -0.542300f
#define PC2  0.871982f
#define PC1 -0.986114f
#define PC0  0.499747f     /* c0 - 0.5 folded */
#define NLOG2E -1.44269504f
#define NLN2   -0.69314718f

__device__ __forceinline__ ull pk2(float lo, float hi) {
    ull r; asm("mov.b64 %0, {%1, %2};" : "=l"(r) : "f"(lo), "f"(hi)); return r;
}
__device__ __forceinline__ void upk2(ull a, float& lo, float& hi) {
    asm("mov.b64 {%0, %1}, %2;" : "=f"(lo), "=f"(hi) : "l"(a));
}
__device__ __forceinline__ ull fma2(ull a, ull b, ull c) {
    ull d; asm("fma.rn.f32x2 %0, %1, %2, %3;" : "=l"(d) : "l"(a), "l"(b), "l"(c)); return d;
}
__device__ __forceinline__ ull add2(ull a, ull b) {
    ull d; asm("add.rn.f32x2 %0, %1, %2;" : "=l"(d) : "l"(a), "l"(b)); return d;
}
__device__ __forceinline__ float ex2a(float x) {
    float y; asm("ex2.approx.f32 %0, %1;" : "=f"(y) : "f"(x)); return y;
}
__device__ __forceinline__ void cp16(uint32_t s, const void* g) {
    asm volatile("cp.async.cg.shared.global [%0], [%1], 16;" :: "r"(s), "l"(g));
}
__device__ __forceinline__ void cp_commit() { asm volatile("cp.async.commit_group;"); }
template<int N> __device__ __forceinline__ void cp_wait() {
    asm volatile("cp.async.wait_group %0;" :: "n"(N));
}

__global__ __launch_bounds__(THREADS, 7)
void fused_attn_mlp_kernel(const float* __restrict__ Q,
                           const float* __restrict__ K,
                           const float* __restrict__ bias,
                           const float* __restrict__ mask,
                           float* __restrict__ out,      // [B,I,C]
                           float* __restrict__ attn)     // [B,I,J]
{
    __shared__ __align__(16) float4 kbuf[2][TJ * KPAD];   // 2 x 8.7KB
    __shared__ __align__(16) float  sbv[C_];              // raw bias

    const int tid  = threadIdx.x;
    const int lane = tid & 31;
    const int w    = tid >> 5;            // warp = local row (0/1)
    const int half = lane >> 4;           // 0: ch 0-31, 1: ch 32-63
    const int lj   = lane & 15;           // j subgroup index
    const int row  = blockIdx.x * ROWS + w;
    const int b    = row >> 10;
    const int h8   = half * 8;            // float4 offset of this channel half

    if (tid < C_) sbv[tid] = bias[tid];

    const uint32_t sb0 = (uint32_t)__cvta_generic_to_shared(&kbuf[0][0]);
    const uint32_t sb1 = (uint32_t)__cvta_generic_to_shared(&kbuf[1][0]);
    const float4* Kb = (const float4*)K + (size_t)b * J_ * 16;

    // prefetch tile 0
    #pragma unroll
    for (int p = 0; p < (TJ * 16) / THREADS; ++p) {
        int idx = tid + p * THREADS;
        int r = idx >> 4, c = idx & 15;
        cp16(sb0 + (uint32_t)(r * KPAD + c) * 16, Kb + (size_t)r * 16 + c);
    }
    cp_commit();

    // q' = -log2e * q  packed pairs (this lane's 32 channels)
    ull q2[16];
    {
        const float4* qrow = (const float4*)(Q + (size_t)row * C_) + h8;
        #pragma unroll
        for (int c = 0; c < 8; ++c) {
            float4 v = qrow[c];
            q2[2*c]   = pk2(NLOG2E * v.x, NLOG2E * v.y);
            q2[2*c+1] = pk2(NLOG2E * v.z, NLOG2E * v.w);
        }
    }

    __syncthreads();   // sbv visible

    // b' = -log2e * bias  packed pairs; and nbsum = -sum(bias)
    ull b2[16];
    float nbsum;
    {
        float s = 0.f;
        const float* bh = sbv + half * 32;
        #pragma unroll
        for (int c = 0; c < 16; ++c) {
            float u0 = bh[2*c], u1 = bh[2*c+1];
            s += u0 + u1;
            b2[c] = pk2(NLOG2E * u0, NLOG2E * u1);
        }
        s += __shfl_xor_sync(0xffffffffu, s, 16);   // full 64-ch bias sum
        nbsum = -s;
    }

    const ull C4 = pk2(PC4, PC4), C3 = pk2(PC3, PC3), C2 = pk2(PC2, PC2),
              C1 = pk2(PC1, PC1), C0 = pk2(PC0, PC0);
    const ull SGN2 = 0x8000000080000000ULL;

    ull acc2[16];
    #pragma unroll
    for (int c = 0; c < 16; ++c) acc2[c] = 0ull;
    float msum = 0.f;

    const float* mrow = mask + (size_t)row * J_;
    float*       arow = attn + (size_t)row * J_;

    for (int t = 0; t < NT; ++t) {
        const float m0 = mrow[t * TJ + lj];
        const float m1 = mrow[t * TJ + 16 + lj];

        if (t + 1 < NT) {
            const float4* src = Kb + (size_t)(t + 1) * TJ * 16;
            uint32_t dst = ((t + 1) & 1) ? sb1 : sb0;
            #pragma unroll
            for (int p = 0; p < (TJ * 16) / THREADS; ++p) {
                int idx = tid + p * THREADS;
                int r = idx >> 4, c = idx & 15;
                cp16(dst + (uint32_t)(r * KPAD + c) * 16, src + (size_t)r * 16 + c);
            }
            cp_commit();
            cp_wait<1>();
        } else {
            cp_wait<0>();
        }
        __syncthreads();

        const float4* kb = kbuf[t & 1];

        #pragma unroll
        for (int u = 0; u < 2; ++u) {
            const int jj = u * 16 + lj;
            const float m = (u == 0) ? m0 : m1;
            const ull  m2 = pk2(m, m);
            const ulonglong2* kr = (const ulonglong2*)(kb + jj * KPAD + h8);

            ull hs2 = 0ull;
            #pragma unroll
            for (int c = 0; c < 8; ++c) {
                const ulonglong2 kk = kr[c];
                #pragma unroll
                for (int p = 0; p < 2; ++p) {
                    const int i = 2*c + p;
                    const ull kp = p ? kk.y : kk.x;
                    const ull xp = fma2(q2[i], kp, b2[i]);   // x' = -log2e*(qk+b)
                    hs2 = add2(hs2, xp);
                    float x0, x1; upk2(xp, x0, x1);
                    const float e0 = ex2a(-fabsf(x0));
                    const float e1 = ex2a(-fabsf(x1));
                    const ull e2 = pk2(e0, e1);
                    ull r = fma2(C4, e2, C3);
                    r = fma2(r, e2, C2);
                    r = fma2(r, e2, C1);
                    r = fma2(r, e2, C0);                     // P(e)-0.5 >= 0
                    const ull rs = r ^ (~xp & SGN2);         // apply sgn(x) = -sgn(x')
                    acc2[i] = fma2(rs, m2, acc2[i]);
                }
            }
            float hl, hh; upk2(hs2, hl, hh);
            float hs = hl + hh;                              // this half's sum of x'
            hs += __shfl_xor_sync(0xffffffffu, hs, 16);      // full 64-ch sum
            // dot(q,k) = -ln2 * sum(x') - sum(bias)
            if (half == 0) arow[t * TJ + jj] = fmaf(hs, NLN2, nbsum) * m;
            msum += m;
        }
        __syncthreads();
    }

    // reduce over the 16 lj lanes (channel halves stay separate)
    #pragma unroll
    for (int s = 1; s < 16; s <<= 1) {
        msum += __shfl_xor_sync(0xffffffffu, msum, s);
        #pragma unroll
        for (int c = 0; c < 16; ++c)
            acc2[c] = add2(acc2[c], __shfl_xor_sync(0xffffffffu, acc2[c], s));
    }

    if (lj == 0) {   // lane 0 writes ch 0-31, lane 16 writes ch 32-63
        const float hm  = 0.5f * msum;
        const float inv = __fdividef(1.0f, msum);
        float* orow = out + (size_t)row * C_ + half * 32;
        #pragma unroll
        for (int c = 0; c < 16; ++c) {
            float a0, a1; upk2(acc2[c], a0, a1);
            float2 o = make_float2((a0 + hm) * inv, (a1 + hm) * inv);
            *(float2*)(orow + 2*c) = o;
        }
    }
}

extern "C" void kernel_launch(void* const* d_in, const int* in_sizes, int n_in,
                              void* d_out, int out_size) {
    const float* Q    = (const float*)d_in[0];
    const float* K    = (const float*)d_in[1];
    const float* bias = (const float*)d_in[2];
    const float* mask = (const float*)d_in[3];
    float* out  = (float*)d_out;                       // [B,I,C] first
    float* attn = (float*)d_out + (size_t)B_*I_*C_;    // [B,I,J] second

    dim3 grid(B_ * I_ / ROWS);
    dim3 block(THREADS);
    fused_attn_mlp_kernel<<<grid, block>>>(Q, K, bias, mask, out, attn);
}